// round 5
// baseline (speedup 1.0000x reference)
#include <cuda_runtime.h>
#include <cuda_fp16.h>
#include <cstdint>
#include <cstddef>

#define TPB     512
#define MB      16          // batch rows per CTA
#define TSTEPS  512
#define HID     128
#define G4      512         // 4*H
#define ISZ     5
#define KTOT    134         // 128 h-rows + 5 x-rows + 1 ones/bias row
#define K2N     67          // KTOT/2
#define HROW    KTOT        // ull (f32x2) entries per H row
#define HBUF    (MB * HROW) // ull per H buffer

// Interleaved W: [k2][n_pair(256)][4 halves: (k even:n even,n odd),(k odd:n even,n odd)]
#define W_HALVES (K2N * 256 * 4)
#define W_BYTES  (W_HALVES * 2)             // 137216
#define H_OFFB   W_BYTES
#define H_BYTES  (2 * HBUF * 8)             // 34304 (double buffer)
#define SMEM_TOTAL (W_BYTES + H_BYTES)      // 171520 < 228KB

typedef unsigned long long ull;

__device__ __forceinline__ ull pack2(float x, float y) {
    ull r;
    asm("mov.b64 %0, {%1, %2};" : "=l"(r)
        : "r"(__float_as_uint(x)), "r"(__float_as_uint(y)));
    return r;
}
__device__ __forceinline__ float2 unpack2(ull v) {
    unsigned a, b;
    asm("mov.b64 {%0, %1}, %2;" : "=r"(a), "=r"(b) : "l"(v));
    return make_float2(__uint_as_float(a), __uint_as_float(b));
}
// Packed fp32x2 FMA (Blackwell FFMA2) — full fp32 precision per lane.
__device__ __forceinline__ void fma2(ull& d, ull a, ull b) {
    asm("fma.rn.f32x2 %0, %1, %2, %0;" : "+l"(d) : "l"(a), "l"(b));
}
__device__ __forceinline__ float sigf(float x) {
    float e = __expf(-x);
    return __fdividef(1.0f, 1.0f + e);
}
__device__ __forceinline__ float tanhf_fast(float x) {
    float e = __expf(-2.0f * x);
    return __fdividef(1.0f - e, 1.0f + e);
}

__global__ void __launch_bounds__(TPB, 1)
lstm_persist(const float* __restrict__ x,     const float* __restrict__ W_ih,
             const float* __restrict__ W_hh,  const float* __restrict__ b_ih,
             const float* __restrict__ b_hh,  const float* __restrict__ W_lin,
             const float* __restrict__ b_lin, float* __restrict__ out)
{
    extern __shared__ char smem[];
    __half* Wsm = reinterpret_cast<__half*>(smem);
    ull* Hbuf = reinterpret_cast<ull*>(smem + H_OFFB);   // 2 × [MB][HROW] of (h,h) f32x2

    const int tid = threadIdx.x;
    const int cg  = tid & 63;        // hidden col-pair index (j0 = 2*cg)
    const int rg  = tid >> 6;        // 8 row groups × 2 rows
    const int r0  = rg << 1;
    const int j0  = cg << 1;
    const int b0  = blockIdx.x * MB;

    // ---- stage W interleaved: half index = (k2*256 + n/2)*4 + ((k&1)<<1 | (n&1)) ----
    for (int e = tid; e < G4 * HID; e += TPB) {          // W_hh[n][k]
        int n = e >> 7, k = e & (HID - 1);
        int idx = (((k >> 1) * 256 + (n >> 1)) << 2) | ((k & 1) << 1) | (n & 1);
        Wsm[idx] = __float2half(W_hh[e]);
    }
    for (int e = tid; e < G4 * ISZ; e += TPB) {          // x-projection rows (k=128+i)
        int n = e / ISZ, i = e - n * ISZ;
        int k = HID + i;
        int idx = (((k >> 1) * 256 + (n >> 1)) << 2) | ((k & 1) << 1) | (n & 1);
        Wsm[idx] = __float2half(W_ih[e]);
    }
    for (int n = tid; n < G4; n += TPB) {                // bias row (k=133)
        int k = KTOT - 1;
        int idx = (((k >> 1) * 256 + (n >> 1)) << 2) | ((k & 1) << 1) | (n & 1);
        Wsm[idx] = __float2half(b_ih[n] + b_hh[n]);
    }

    // ---- init both H buffers: h=0, ones row; x(0) into buffer 0 ----
    for (int e = tid; e < MB * HID; e += TPB) {
        int r = e >> 7, k = e & (HID - 1);
        Hbuf[r * HROW + k] = 0ull;
        Hbuf[HBUF + r * HROW + k] = 0ull;
    }
    if (tid < MB) {
        Hbuf[tid * HROW + (KTOT - 1)] = pack2(1.0f, 1.0f);
        Hbuf[HBUF + tid * HROW + (KTOT - 1)] = pack2(1.0f, 1.0f);
    }
    if (tid < MB * ISZ) {
        int r = tid / ISZ, i = tid - r * ISZ;
        float v = x[(size_t)(b0 + r) * (TSTEPS * ISZ) + i];
        Hbuf[r * HROW + HID + i] = pack2(v, v);
        Hbuf[HBUF + r * HROW + HID + i] = 0ull;   // overwritten by prefetch anyway
    }

    float c_st[2][2];
    c_st[0][0] = c_st[0][1] = c_st[1][0] = c_st[1][1] = 0.f;

    __syncthreads();

    for (int t = 0; t < TSTEPS; t++) {
        const ull* __restrict__ Hrd = Hbuf + (size_t)(t & 1) * HBUF;
        ull* __restrict__       Hwr = Hbuf + (size_t)((t & 1) ^ 1) * HBUF;

        ull acc[2][4];
        #pragma unroll
        for (int a = 0; a < 2; a++)
            #pragma unroll
            for (int g = 0; g < 4; g++) acc[a][g] = 0ull;

        #pragma unroll 4
        for (int k2 = 0; k2 < K2N; k2++) {
            // broadcast LDS.128: (h_k,h_k),(h_{k+1},h_{k+1}) for both rows
            ulonglong2 hv0 = *reinterpret_cast<const ulonglong2*>(&Hrd[r0 * HROW + (k2 << 1)]);
            ulonglong2 hv1 = *reinterpret_cast<const ulonglong2*>(&Hrd[(r0 + 1) * HROW + (k2 << 1)]);
            #pragma unroll
            for (int g = 0; g < 4; g++) {
                uint2 wraw = *reinterpret_cast<const uint2*>(
                    &Wsm[((k2 * 256 + (g << 6) + cg) << 2)]);
                float2 w0 = __half22float2(*reinterpret_cast<const __half2*>(&wraw.x));
                float2 w1 = __half22float2(*reinterpret_cast<const __half2*>(&wraw.y));
                ull wb0 = pack2(w0.x, w0.y);
                ull wb1 = pack2(w1.x, w1.y);
                fma2(acc[0][g], hv0.x, wb0);
                fma2(acc[0][g], hv0.y, wb1);
                fma2(acc[1][g], hv1.x, wb0);
                fma2(acc[1][g], hv1.y, wb1);
            }
        }

        // prefetch x(t+1) into the write buffer (hidden behind activations)
        float xnv = 0.f; int xr = 0, xi = 0;
        const bool do_x = (tid < MB * ISZ) && (t + 1 < TSTEPS);
        if (do_x) {
            xr = tid / ISZ; xi = tid - xr * ISZ;
            xnv = x[(size_t)(b0 + xr) * (TSTEPS * ISZ) + (size_t)(t + 1) * ISZ + xi];
        }

        // activations: thread-local c, write (h,h) pairs into Hwr
        #pragma unroll
        for (int a = 0; a < 2; a++) {
            float2 gi = unpack2(acc[a][0]);
            float2 gf = unpack2(acc[a][1]);
            float2 gg = unpack2(acc[a][2]);
            float2 go = unpack2(acc[a][3]);
            float c0 = sigf(gf.x) * c_st[a][0] + sigf(gi.x) * tanhf_fast(gg.x);
            float c1 = sigf(gf.y) * c_st[a][1] + sigf(gi.y) * tanhf_fast(gg.y);
            c_st[a][0] = c0; c_st[a][1] = c1;
            float h0 = sigf(go.x) * tanhf_fast(c0);
            float h1 = sigf(go.y) * tanhf_fast(c1);
            ulonglong2 hw;
            hw.x = pack2(h0, h0);
            hw.y = pack2(h1, h1);
            *reinterpret_cast<ulonglong2*>(&Hwr[(r0 + a) * HROW + j0]) = hw;
        }

        if (do_x) Hwr[xr * HROW + HID + xi] = pack2(xnv, xnv);

        __syncthreads();   // single barrier per step (double-buffered H)
    }

    // ---- epilogue: out[b] = h_n . W_lin + b_lin  (final h is in buffer 0) ----
    if (tid < 128) {
        const int row = tid >> 3, seg = tid & 7;
        float s = 0.f;
        #pragma unroll
        for (int jj = 0; jj < 16; jj++) {
            int j = (seg << 4) + jj;
            s += unpack2(Hbuf[row * HROW + j]).x * W_lin[j];
        }
        s += __shfl_xor_sync(0xffffffffu, s, 4);
        s += __shfl_xor_sync(0xffffffffu, s, 2);
        s += __shfl_xor_sync(0xffffffffu, s, 1);
        if (seg == 0) out[b0 + row] = s + b_lin[0];
    }
}

extern "C" void kernel_launch(void* const* d_in, const int* in_sizes, int n_in,
                              void* d_out, int out_size) {
    const float* x     = (const float*)d_in[0];
    const float* W_ih  = (const float*)d_in[1];
    const float* W_hh  = (const float*)d_in[2];
    const float* b_ih  = (const float*)d_in[3];
    const float* b_hh  = (const float*)d_in[4];
    const float* W_lin = (const float*)d_in[5];
    const float* b_lin = (const float*)d_in[6];
    float* out = (float*)d_out;

    int B    = in_sizes[0] / (TSTEPS * ISZ);   // 2048
    int nCTA = B / MB;                          // 128 CTAs -> one wave

    cudaFuncSetAttribute(lstm_persist,
                         cudaFuncAttributeMaxDynamicSharedMemorySize, SMEM_TOTAL);
    lstm_persist<<<nCTA, TPB, SMEM_TOTAL>>>(x, W_ih, W_hh, b_ih, b_hh,
                                            W_lin, b_lin, out);
}

// round 6
// speedup vs baseline: 1.3892x; 1.3892x over previous
#include <cuda_runtime.h>
#include <cuda_fp16.h>
#include <cstdint>
#include <cstddef>

#define TPB     256
#define MB      16          // batch rows per CTA
#define TSTEPS  512
#define HID     128
#define G4      512         // 4*H
#define ISZ     5
#define KTOT    136         // 128 h + 5 x + 1 bias + 2 zero-pad
#define K2N     68          // KTOT/2 (unrolls by 4 cleanly)
#define HROW    KTOT        // ull (f32x2) entries per H row

// W32: gates 0,1 (i,f) as float4 {w(k,j0),w(k,j0+1),w(k+1,j0),w(k+1,j0+1)}
#define W32_BYTES (K2N * 2 * 64 * 16)       // 139264
// W16: gates 2,3 (g,o) as uint2 {half2(k,j0/j0+1), half2(k+1,...)}
#define W16_OFFB  W32_BYTES
#define W16_BYTES (K2N * 2 * 64 * 8)        // 69632
#define H_OFFB    (W32_BYTES + W16_BYTES)   // 208896
#define H_BYTES   (MB * HROW * 8)           // 17408
#define SMEM_TOTAL (H_OFFB + H_BYTES)       // 226304 <= 232448

typedef unsigned long long ull;

__device__ __forceinline__ ull pack2(float x, float y) {
    ull r;
    asm("mov.b64 %0, {%1, %2};" : "=l"(r)
        : "r"(__float_as_uint(x)), "r"(__float_as_uint(y)));
    return r;
}
__device__ __forceinline__ float2 unpack2(ull v) {
    unsigned a, b;
    asm("mov.b64 {%0, %1}, %2;" : "=r"(a), "=r"(b) : "l"(v));
    return make_float2(__uint_as_float(a), __uint_as_float(b));
}
// Packed fp32x2 FMA (Blackwell FFMA2) — full fp32 precision per lane.
__device__ __forceinline__ void fma2(ull& d, ull a, ull b) {
    asm("fma.rn.f32x2 %0, %1, %2, %0;" : "+l"(d) : "l"(a), "l"(b));
}
__device__ __forceinline__ ull h2_to_f32x2(unsigned h2raw) {
    float2 f = __half22float2(*reinterpret_cast<const __half2*>(&h2raw));
    return pack2(f.x, f.y);
}
__device__ __forceinline__ float sigf(float x) {
    float e = __expf(-x);
    return __fdividef(1.0f, 1.0f + e);
}
__device__ __forceinline__ float tanhf_fast(float x) {
    float e = __expf(-2.0f * x);
    return __fdividef(1.0f - e, 1.0f + e);
}

__global__ void __launch_bounds__(TPB, 1)
lstm_persist(const float* __restrict__ x,     const float* __restrict__ W_ih,
             const float* __restrict__ W_hh,  const float* __restrict__ b_ih,
             const float* __restrict__ b_hh,  const float* __restrict__ W_lin,
             const float* __restrict__ b_lin, float* __restrict__ out)
{
    extern __shared__ char smem[];
    float*  W32 = reinterpret_cast<float*>(smem);
    __half* W16 = reinterpret_cast<__half*>(smem + W16_OFFB);
    ull*    Hsm = reinterpret_cast<ull*>(smem + H_OFFB);   // [MB][HROW] of (h,h) f32x2
    const ulonglong2* W32u = reinterpret_cast<const ulonglong2*>(smem);
    const uint2*      W16u = reinterpret_cast<const uint2*>(smem + W16_OFFB);

    const int tid   = threadIdx.x;
    const int cg    = tid & 63;        // hidden col-pair (j0 = 2*cg)
    const int rg    = tid >> 6;        // 4 row groups, 4 rows each, 64 threads each
    const int local = tid & 63;
    const int r0    = rg << 2;
    const int j0    = cg << 1;
    const int b0    = blockIdx.x * MB;
    const int barid = rg + 1;          // named barrier per row group

    // ---- stage W: gates 0,1 fp32 pre-packed pairs; gates 2,3 fp16 interleaved ----
    for (int e = tid; e < KTOT * G4; e += TPB) {
        int k = e >> 9;            // 0..135
        int n = e & 511;
        float val;
        if (k < HID)           val = W_hh[n * HID + k];
        else if (k < HID + ISZ) val = W_ih[n * ISZ + (k - HID)];
        else if (k == 133)     val = b_ih[n] + b_hh[n];
        else                   val = 0.f;                   // zero pad rows
        int g = n >> 7, j = n & 127;
        int k2 = k >> 1;
        int slot = ((k & 1) << 1) | (j & 1);
        int grp  = ((k2 * 2 + (g & 1)) << 6) + (j >> 1);
        if (g < 2) W32[(grp << 2) + slot] = val;
        else       W16[(grp << 2) + slot] = __float2half(val);
    }

    // ---- init H: h=0, x(t=0), ones row at k=133, zero pads ----
    for (int e = tid; e < MB * HROW; e += TPB) Hsm[e] = 0ull;
    __syncthreads();
    if (local < 4) {
        int r = r0 + local;
        Hsm[r * HROW + 133] = pack2(1.0f, 1.0f);
    }
    if (local < 4 * ISZ) {
        int r = r0 + local / ISZ, i = local % ISZ;
        float v = x[(size_t)(b0 + r) * (TSTEPS * ISZ) + i];
        Hsm[r * HROW + HID + i] = pack2(v, v);
    }

    float c_st[4][2];
    #pragma unroll
    for (int a = 0; a < 4; a++) { c_st[a][0] = 0.f; c_st[a][1] = 0.f; }

    __syncthreads();

    for (int t = 0; t < TSTEPS; t++) {
        ull acc[4][4];
        #pragma unroll
        for (int a = 0; a < 4; a++)
            #pragma unroll
            for (int g = 0; g < 4; g++) acc[a][g] = 0ull;

        #pragma unroll 4
        for (int k2 = 0; k2 < K2N; k2++) {
            // warp-uniform broadcast: (h_k,h_k),(h_{k+1},h_{k+1}) for 4 rows
            ulonglong2 hv0 = *reinterpret_cast<const ulonglong2*>(&Hsm[(r0 + 0) * HROW + (k2 << 1)]);
            ulonglong2 hv1 = *reinterpret_cast<const ulonglong2*>(&Hsm[(r0 + 1) * HROW + (k2 << 1)]);
            ulonglong2 hv2 = *reinterpret_cast<const ulonglong2*>(&Hsm[(r0 + 2) * HROW + (k2 << 1)]);
            ulonglong2 hv3 = *reinterpret_cast<const ulonglong2*>(&Hsm[(r0 + 3) * HROW + (k2 << 1)]);

            // gates 0,1: fp32 pre-packed — zero cvt/pack
            ulonglong2 wg0 = W32u[((k2 * 2 + 0) << 6) + cg];   // .x=k slice, .y=k+1 slice
            ulonglong2 wg1 = W32u[((k2 * 2 + 1) << 6) + cg];
            // gates 2,3: fp16
            uint2 r2 = W16u[((k2 * 2 + 0) << 6) + cg];
            uint2 r3 = W16u[((k2 * 2 + 1) << 6) + cg];
            ull wg2x = h2_to_f32x2(r2.x), wg2y = h2_to_f32x2(r2.y);
            ull wg3x = h2_to_f32x2(r3.x), wg3y = h2_to_f32x2(r3.y);

            fma2(acc[0][0], hv0.x, wg0.x); fma2(acc[0][0], hv0.y, wg0.y);
            fma2(acc[1][0], hv1.x, wg0.x); fma2(acc[1][0], hv1.y, wg0.y);
            fma2(acc[2][0], hv2.x, wg0.x); fma2(acc[2][0], hv2.y, wg0.y);
            fma2(acc[3][0], hv3.x, wg0.x); fma2(acc[3][0], hv3.y, wg0.y);

            fma2(acc[0][1], hv0.x, wg1.x); fma2(acc[0][1], hv0.y, wg1.y);
            fma2(acc[1][1], hv1.x, wg1.x); fma2(acc[1][1], hv1.y, wg1.y);
            fma2(acc[2][1], hv2.x, wg1.x); fma2(acc[2][1], hv2.y, wg1.y);
            fma2(acc[3][1], hv3.x, wg1.x); fma2(acc[3][1], hv3.y, wg1.y);

            fma2(acc[0][2], hv0.x, wg2x); fma2(acc[0][2], hv0.y, wg2y);
            fma2(acc[1][2], hv1.x, wg2x); fma2(acc[1][2], hv1.y, wg2y);
            fma2(acc[2][2], hv2.x, wg2x); fma2(acc[2][2], hv2.y, wg2y);
            fma2(acc[3][2], hv3.x, wg2x); fma2(acc[3][2], hv3.y, wg2y);

            fma2(acc[0][3], hv0.x, wg3x); fma2(acc[0][3], hv0.y, wg3y);
            fma2(acc[1][3], hv1.x, wg3x); fma2(acc[1][3], hv1.y, wg3y);
            fma2(acc[2][3], hv2.x, wg3x); fma2(acc[2][3], hv2.y, wg3y);
            fma2(acc[3][3], hv3.x, wg3x); fma2(acc[3][3], hv3.y, wg3y);
        }

        // prefetch x(t+1) (LDG issued before the barrier; stored after)
        float xnv = 0.f; int xr = 0, xi = 0;
        const bool do_x = (local < 4 * ISZ) && (t + 1 < TSTEPS);
        if (do_x) {
            xr = r0 + local / ISZ; xi = local % ISZ;
            xnv = x[(size_t)(b0 + xr) * (TSTEPS * ISZ) + (size_t)(t + 1) * ISZ + xi];
        }

        // group barrier: this group's 4 rows are read/written only by these 64 threads
        asm volatile("bar.sync %0, 64;" :: "r"(barid) : "memory");

        #pragma unroll
        for (int a = 0; a < 4; a++) {
            float2 gi = unpack2(acc[a][0]);
            float2 gf = unpack2(acc[a][1]);
            float2 gg = unpack2(acc[a][2]);
            float2 go = unpack2(acc[a][3]);
            float c0 = sigf(gf.x) * c_st[a][0] + sigf(gi.x) * tanhf_fast(gg.x);
            float c1 = sigf(gf.y) * c_st[a][1] + sigf(gi.y) * tanhf_fast(gg.y);
            c_st[a][0] = c0; c_st[a][1] = c1;
            float h0 = sigf(go.x) * tanhf_fast(c0);
            float h1 = sigf(go.y) * tanhf_fast(c1);
            ulonglong2 hw;
            hw.x = pack2(h0, h0);
            hw.y = pack2(h1, h1);
            *reinterpret_cast<ulonglong2*>(&Hsm[(r0 + a) * HROW + j0]) = hw;
        }
        if (do_x) Hsm[xr * HROW + HID + xi] = pack2(xnv, xnv);

        asm volatile("bar.sync %0, 64;" :: "r"(barid) : "memory");
    }

    __syncthreads();

    // ---- epilogue: out[b] = h_n . W_lin + b_lin ----
    if (tid < 128) {
        const int row = tid >> 3, seg = tid & 7;
        float s = 0.f;
        #pragma unroll
        for (int jj = 0; jj < 16; jj++) {
            int j = (seg << 4) + jj;
            s += unpack2(Hsm[row * HROW + j]).x * W_lin[j];
        }
        s += __shfl_xor_sync(0xffffffffu, s, 4);
        s += __shfl_xor_sync(0xffffffffu, s, 2);
        s += __shfl_xor_sync(0xffffffffu, s, 1);
        if (seg == 0) out[b0 + row] = s + b_lin[0];
    }
}

extern "C" void kernel_launch(void* const* d_in, const int* in_sizes, int n_in,
                              void* d_out, int out_size) {
    const float* x     = (const float*)d_in[0];
    const float* W_ih  = (const float*)d_in[1];
    const float* W_hh  = (const float*)d_in[2];
    const float* b_ih  = (const float*)d_in[3];
    const float* b_hh  = (const float*)d_in[4];
    const float* W_lin = (const float*)d_in[5];
    const float* b_lin = (const float*)d_in[6];
    float* out = (float*)d_out;

    int B    = in_sizes[0] / (TSTEPS * ISZ);   // 2048
    int nCTA = B / MB;                          // 128 CTAs, one wave

    cudaFuncSetAttribute(lstm_persist,
                         cudaFuncAttributeMaxDynamicSharedMemorySize, SMEM_TOTAL);
    lstm_persist<<<nCTA, TPB, SMEM_TOTAL>>>(x, W_ih, W_hh, b_ih, b_hh,
                                            W_lin, b_lin, out);
}

// round 7
// speedup vs baseline: 1.3900x; 1.0005x over previous
#include <cuda_runtime.h>
#include <cuda_fp16.h>
#include <cstdint>
#include <cstddef>

#define TPB     256
#define MB      16          // batch rows per CTA
#define TSTEPS  512
#define HID     128
#define G4      512         // 4*H
#define ISZ     5
#define KTOT    136         // 128 h + 5 x + 1 bias + 2 zero-pad
#define K2N     68          // KTOT/2 (unrolls by 4 cleanly)
#define HROW    KTOT        // ull (f32x2) entries per H row

// W32: gates 0,1 (i,f) as float4 {w(k,j0),w(k,j0+1),w(k+1,j0),w(k+1,j0+1)}
#define W32_BYTES (K2N * 2 * 64 * 16)       // 139264
// W16: gates 2,3 (g,o) as uint2 {half2(k,j0/j0+1), half2(k+1,...)}
#define W16_OFFB  W32_BYTES
#define W16_BYTES (K2N * 2 * 64 * 8)        // 69632
#define H_OFFB    (W32_BYTES + W16_BYTES)   // 208896
#define H_BYTES   (MB * HROW * 8)           // 17408
#define SMEM_TOTAL (H_OFFB + H_BYTES)       // 226304 <= 232448

typedef unsigned long long ull;

__device__ __forceinline__ ull pack2(float x, float y) {
    ull r;
    asm("mov.b64 %0, {%1, %2};" : "=l"(r)
        : "r"(__float_as_uint(x)), "r"(__float_as_uint(y)));
    return r;
}
__device__ __forceinline__ float2 unpack2(ull v) {
    unsigned a, b;
    asm("mov.b64 {%0, %1}, %2;" : "=r"(a), "=r"(b) : "l"(v));
    return make_float2(__uint_as_float(a), __uint_as_float(b));
}
// Packed fp32x2 FMA (Blackwell FFMA2) — full fp32 precision per lane.
__device__ __forceinline__ void fma2(ull& d, ull a, ull b) {
    asm("fma.rn.f32x2 %0, %1, %2, %0;" : "+l"(d) : "l"(a), "l"(b));
}
__device__ __forceinline__ ull h2_to_f32x2(unsigned h2raw) {
    float2 f = __half22float2(*reinterpret_cast<const __half2*>(&h2raw));
    return pack2(f.x, f.y);
}
__device__ __forceinline__ float sigf(float x) {
    float e = __expf(-x);
    return __fdividef(1.0f, 1.0f + e);
}
__device__ __forceinline__ float tanhf_fast(float x) {
    float e = __expf(-2.0f * x);
    return __fdividef(1.0f - e, 1.0f + e);
}

__global__ void __launch_bounds__(TPB, 1)
lstm_persist(const float* __restrict__ x,     const float* __restrict__ W_ih,
             const float* __restrict__ W_hh,  const float* __restrict__ b_ih,
             const float* __restrict__ b_hh,  const float* __restrict__ W_lin,
             const float* __restrict__ b_lin, float* __restrict__ out)
{
    extern __shared__ char smem[];
    float*  W32 = reinterpret_cast<float*>(smem);
    __half* W16 = reinterpret_cast<__half*>(smem + W16_OFFB);
    ull*    Hsm = reinterpret_cast<ull*>(smem + H_OFFB);   // [MB][HROW] of (h,h) f32x2
    const ulonglong2* W32u = reinterpret_cast<const ulonglong2*>(smem);
    const uint2*      W16u = reinterpret_cast<const uint2*>(smem + W16_OFFB);

    const int tid   = threadIdx.x;
    const int cg    = tid & 63;        // hidden col-pair (j0 = 2*cg)
    const int rg    = tid >> 6;        // 4 row groups, 4 rows each, 64 threads each
    const int local = tid & 63;
    const int r0    = rg << 2;
    const int j0    = cg << 1;
    const int b0    = blockIdx.x * MB;
    const int barid = rg + 1;          // named barrier per row group

    // ---- stage W: gates 0,1 fp32 pre-packed pairs; gates 2,3 fp16 interleaved ----
    for (int e = tid; e < KTOT * G4; e += TPB) {
        int k = e >> 9;            // 0..135
        int n = e & 511;
        float val;
        if (k < HID)           val = W_hh[n * HID + k];
        else if (k < HID + ISZ) val = W_ih[n * ISZ + (k - HID)];
        else if (k == 133)     val = b_ih[n] + b_hh[n];
        else                   val = 0.f;                   // zero pad rows
        int g = n >> 7, j = n & 127;
        int k2 = k >> 1;
        int slot = ((k & 1) << 1) | (j & 1);
        int grp  = ((k2 * 2 + (g & 1)) << 6) + (j >> 1);
        if (g < 2) W32[(grp << 2) + slot] = val;
        else       W16[(grp << 2) + slot] = __float2half(val);
    }

    // ---- init H: h=0, x(t=0), ones row at k=133, zero pads ----
    for (int e = tid; e < MB * HROW; e += TPB) Hsm[e] = 0ull;
    __syncthreads();
    if (local < 4) {
        int r = r0 + local;
        Hsm[r * HROW + 133] = pack2(1.0f, 1.0f);
    }
    if (local < 4 * ISZ) {
        int r = r0 + local / ISZ, i = local % ISZ;
        float v = x[(size_t)(b0 + r) * (TSTEPS * ISZ) + i];
        Hsm[r * HROW + HID + i] = pack2(v, v);
    }

    float c_st[4][2];
    #pragma unroll
    for (int a = 0; a < 4; a++) { c_st[a][0] = 0.f; c_st[a][1] = 0.f; }

    __syncthreads();

    for (int t = 0; t < TSTEPS; t++) {
        ull acc[4][4];
        #pragma unroll
        for (int a = 0; a < 4; a++)
            #pragma unroll
            for (int g = 0; g < 4; g++) acc[a][g] = 0ull;

        #pragma unroll 4
        for (int k2 = 0; k2 < K2N; k2++) {
            // warp-uniform broadcast: (h_k,h_k),(h_{k+1},h_{k+1}) for 4 rows
            ulonglong2 hv0 = *reinterpret_cast<const ulonglong2*>(&Hsm[(r0 + 0) * HROW + (k2 << 1)]);
            ulonglong2 hv1 = *reinterpret_cast<const ulonglong2*>(&Hsm[(r0 + 1) * HROW + (k2 << 1)]);
            ulonglong2 hv2 = *reinterpret_cast<const ulonglong2*>(&Hsm[(r0 + 2) * HROW + (k2 << 1)]);
            ulonglong2 hv3 = *reinterpret_cast<const ulonglong2*>(&Hsm[(r0 + 3) * HROW + (k2 << 1)]);

            // gates 0,1: fp32 pre-packed — zero cvt/pack
            ulonglong2 wg0 = W32u[((k2 * 2 + 0) << 6) + cg];   // .x=k slice, .y=k+1 slice
            ulonglong2 wg1 = W32u[((k2 * 2 + 1) << 6) + cg];
            // gates 2,3: fp16
            uint2 r2 = W16u[((k2 * 2 + 0) << 6) + cg];
            uint2 r3 = W16u[((k2 * 2 + 1) << 6) + cg];
            ull wg2x = h2_to_f32x2(r2.x), wg2y = h2_to_f32x2(r2.y);
            ull wg3x = h2_to_f32x2(r3.x), wg3y = h2_to_f32x2(r3.y);

            fma2(acc[0][0], hv0.x, wg0.x); fma2(acc[0][0], hv0.y, wg0.y);
            fma2(acc[1][0], hv1.x, wg0.x); fma2(acc[1][0], hv1.y, wg0.y);
            fma2(acc[2][0], hv2.x, wg0.x); fma2(acc[2][0], hv2.y, wg0.y);
            fma2(acc[3][0], hv3.x, wg0.x); fma2(acc[3][0], hv3.y, wg0.y);

            fma2(acc[0][1], hv0.x, wg1.x); fma2(acc[0][1], hv0.y, wg1.y);
            fma2(acc[1][1], hv1.x, wg1.x); fma2(acc[1][1], hv1.y, wg1.y);
            fma2(acc[2][1], hv2.x, wg1.x); fma2(acc[2][1], hv2.y, wg1.y);
            fma2(acc[3][1], hv3.x, wg1.x); fma2(acc[3][1], hv3.y, wg1.y);

            fma2(acc[0][2], hv0.x, wg2x); fma2(acc[0][2], hv0.y, wg2y);
            fma2(acc[1][2], hv1.x, wg2x); fma2(acc[1][2], hv1.y, wg2y);
            fma2(acc[2][2], hv2.x, wg2x); fma2(acc[2][2], hv2.y, wg2y);
            fma2(acc[3][2], hv3.x, wg2x); fma2(acc[3][2], hv3.y, wg2y);

            fma2(acc[0][3], hv0.x, wg3x); fma2(acc[0][3], hv0.y, wg3y);
            fma2(acc[1][3], hv1.x, wg3x); fma2(acc[1][3], hv1.y, wg3y);
            fma2(acc[2][3], hv2.x, wg3x); fma2(acc[2][3], hv2.y, wg3y);
            fma2(acc[3][3], hv3.x, wg3x); fma2(acc[3][3], hv3.y, wg3y);
        }

        // prefetch x(t+1) (LDG issued before the barrier; stored after)
        float xnv = 0.f; int xr = 0, xi = 0;
        const bool do_x = (local < 4 * ISZ) && (t + 1 < TSTEPS);
        if (do_x) {
            xr = r0 + local / ISZ; xi = local % ISZ;
            xnv = x[(size_t)(b0 + xr) * (TSTEPS * ISZ) + (size_t)(t + 1) * ISZ + xi];
        }

        // group barrier: this group's 4 rows are read/written only by these 64 threads
        asm volatile("bar.sync %0, 64;" :: "r"(barid) : "memory");

        #pragma unroll
        for (int a = 0; a < 4; a++) {
            float2 gi = unpack2(acc[a][0]);
            float2 gf = unpack2(acc[a][1]);
            float2 gg = unpack2(acc[a][2]);
            float2 go = unpack2(acc[a][3]);
            float c0 = sigf(gf.x) * c_st[a][0] + sigf(gi.x) * tanhf_fast(gg.x);
            float c1 = sigf(gf.y) * c_st[a][1] + sigf(gi.y) * tanhf_fast(gg.y);
            c_st[a][0] = c0; c_st[a][1] = c1;
            float h0 = sigf(go.x) * tanhf_fast(c0);
            float h1 = sigf(go.y) * tanhf_fast(c1);
            ulonglong2 hw;
            hw.x = pack2(h0, h0);
            hw.y = pack2(h1, h1);
            *reinterpret_cast<ulonglong2*>(&Hsm[(r0 + a) * HROW + j0]) = hw;
        }
        if (do_x) Hsm[xr * HROW + HID + xi] = pack2(xnv, xnv);

        asm volatile("bar.sync %0, 64;" :: "r"(barid) : "memory");
    }

    __syncthreads();

    // ---- epilogue: out[b] = h_n . W_lin + b_lin ----
    if (tid < 128) {
        const int row = tid >> 3, seg = tid & 7;
        float s = 0.f;
        #pragma unroll
        for (int jj = 0; jj < 16; jj++) {
            int j = (seg << 4) + jj;
            s += unpack2(Hsm[row * HROW + j]).x * W_lin[j];
        }
        s += __shfl_xor_sync(0xffffffffu, s, 4);
        s += __shfl_xor_sync(0xffffffffu, s, 2);
        s += __shfl_xor_sync(0xffffffffu, s, 1);
        if (seg == 0) out[b0 + row] = s + b_lin[0];
    }
}

extern "C" void kernel_launch(void* const* d_in, const int* in_sizes, int n_in,
                              void* d_out, int out_size) {
    const float* x     = (const float*)d_in[0];
    const float* W_ih  = (const float*)d_in[1];
    const float* W_hh  = (const float*)d_in[2];
    const float* b_ih  = (const float*)d_in[3];
    const float* b_hh  = (const float*)d_in[4];
    const float* W_lin = (const float*)d_in[5];
    const float* b_lin = (const float*)d_in[6];
    float* out = (float*)d_out;

    int B    = in_sizes[0] / (TSTEPS * ISZ);   // 2048
    int nCTA = B / MB;                          // 128 CTAs, one wave

    cudaFuncSetAttribute(lstm_persist,
                         cudaFuncAttributeMaxDynamicSharedMemorySize, SMEM_TOTAL);
    lstm_persist<<<nCTA, TPB, SMEM_TOTAL>>>(x, W_ih, W_hh, b_ih, b_hh,
                                            W_lin, b_lin, out);
}

// round 9
// speedup vs baseline: 7.3184x; 5.2652x over previous
#include <cuda_runtime.h>
#include <cuda_fp16.h>
#include <cstdint>
#include <cstddef>

#define TPB     256
#define MB      16            // batch rows per CTA
#define TSTEPS  512
#define ISZ     5
#define TI      (TSTEPS*ISZ)
#define HID     128
#define KTOT    144           // 128 h + 5 x + 1 bias + 10 zero pad
#define KCH     9             // K chunks of 16
#define WSTR    152           // halves per row (304B: 8-row ldmatrix stride conflict-free)

#define B_BYTES   (512*WSTR*2)       // 155648
#define A_BYTES   (MB*WSTR*2)        // 4864 per buffer
#define SMEM_B    0
#define SMEM_A0   B_BYTES
#define SMEM_A1   (SMEM_A0 + A_BYTES)
#define SMEM_P    (SMEM_A1 + A_BYTES)
#define SMEM_TOTAL (SMEM_P + MB*8*4) // 165888

__device__ __forceinline__ uint32_t smem_u32(const void* p) {
    uint32_t a;
    asm("{ .reg .u64 t; cvta.to.shared.u64 t, %1; cvt.u32.u64 %0, t; }" : "=r"(a) : "l"(p));
    return a;
}
#define LDSM4(r0, r1, r2, r3, addr) \
    asm volatile("ldmatrix.sync.aligned.m8n8.x4.shared.b16 {%0,%1,%2,%3}, [%4];" \
        : "=r"(r0), "=r"(r1), "=r"(r2), "=r"(r3) : "r"(addr))
#define MMA16816(d, a0, a1, a2, a3, b0, b1) \
    asm volatile("mma.sync.aligned.m16n8k16.row.col.f32.f16.f16.f32 " \
        "{%0,%1,%2,%3}, {%4,%5,%6,%7}, {%8,%9}, {%0,%1,%2,%3};" \
        : "+f"((d)[0]), "+f"((d)[1]), "+f"((d)[2]), "+f"((d)[3]) \
        : "r"(a0), "r"(a1), "r"(a2), "r"(a3), "r"(b0), "r"(b1))

__device__ __forceinline__ float tanha(float x) {
    float r; asm("tanh.approx.f32 %0, %1;" : "=f"(r) : "f"(x)); return r;
}
__device__ __forceinline__ float siga(float x) {
    return fmaf(0.5f, tanha(0.5f * x), 0.5f);
}

__global__ void __launch_bounds__(TPB, 1)
lstm_hmma(const float* __restrict__ x,     const float* __restrict__ W_ih,
          const float* __restrict__ W_hh,  const float* __restrict__ b_ih,
          const float* __restrict__ b_hh,  const float* __restrict__ W_lin,
          const float* __restrict__ b_lin, float* __restrict__ out)
{
    extern __shared__ char smem[];
    const uint32_t sb = smem_u32(smem);
    const int tid = threadIdx.x;
    const int w = tid >> 5, l = tid & 31;
    const int q = l >> 2, m = l & 3;
    const int b0 = blockIdx.x * MB;

    // ---- stage B = W, fp16 [n][k], n = j*4 + g interleaved ----
    for (int e = tid; e < 512 * KTOT; e += TPB) {
        int ni = e / KTOT, k = e - ni * KTOT;
        int g = ni & 3, j = ni >> 2;
        int nsrc = g * HID + j;
        float v = 0.f;
        if (k < HID)        v = W_hh[nsrc * HID + k];
        else if (k < 133)   v = W_ih[nsrc * ISZ + (k - HID)];
        else if (k == 133)  v = b_ih[nsrc] + b_hh[nsrc];
        *reinterpret_cast<__half*>(smem + SMEM_B + (size_t)(ni * WSTR + k) * 2) = __float2half(v);
    }
    // ---- zero A buffers ----
    for (int i = tid; i < 2 * A_BYTES / 4; i += TPB)
        reinterpret_cast<uint32_t*>(smem + SMEM_A0)[i] = 0u;
    __syncthreads();
    // bias col (both buffers) + x(t=0) into buffer 0
    if (tid < MB) {
        *reinterpret_cast<__half*>(smem + SMEM_A0 + (tid * WSTR + 133) * 2) = __float2half(1.f);
        *reinterpret_cast<__half*>(smem + SMEM_A1 + (tid * WSTR + 133) * 2) = __float2half(1.f);
    }
    if (tid < MB * ISZ) {
        int r = tid / ISZ, i = tid - r * ISZ;
        *reinterpret_cast<__half*>(smem + SMEM_A0 + (r * WSTR + HID + i) * 2) =
            __float2half(x[(size_t)(b0 + r) * TI + i]);
    }

    // ---- per-lane ldmatrix addresses ----
    // A x4: m0 rows0-7 klo, m1 rows8-15 klo, m2 rows0-7 khi, m3 rows8-15 khi
    const uint32_t a_lane = sb + SMEM_A0 +
        (uint32_t)(((((l >> 3) & 1) * 8 + (l & 7)) * WSTR + ((l >> 4) & 1) * 8) * 2);
    // B x4: m0 (n0-7, klo), m1 (n0-7, khi), m2 (n8-15, klo), m3 (n8-15, khi)
    const uint32_t b_lane = sb + SMEM_B +
        (uint32_t)(((64 * w + ((l >> 4) & 1) * 8 + (l & 7)) * WSTR + ((l >> 3) & 1) * 8) * 2);

    float wl[8], c_st[8];
    #pragma unroll
    for (int ti = 0; ti < 8; ti++) {
        wl[ti] = W_lin[16 * w + 2 * ti + (m >> 1)];
        c_st[ti] = 0.f;
    }
    const int rowm = q + 8 * (m & 1);    // this lane's output row after gate exchange
    float p_out = 0.f;

    for (int t = 0; t < TSTEPS; t++) {
        __syncthreads();                     // A[read] fully written
        const int rb = t & 1;
        const uint32_t Ard = a_lane + (uint32_t)(rb ? A_BYTES : 0);

        // x(t+1) prefetch (LDG early; stored into write buffer after MMA)
        float xv = 0.f; int xr = 0, xi = 0;
        const bool dox = (tid < MB * ISZ) && (t + 1 < TSTEPS);
        if (dox) {
            xr = tid / ISZ; xi = tid - xr * ISZ;
            xv = x[(size_t)(b0 + xr) * TI + (size_t)(t + 1) * ISZ + xi];
        }

        float C[8][4];
        #pragma unroll
        for (int ti = 0; ti < 8; ti++)
            C[ti][0] = C[ti][1] = C[ti][2] = C[ti][3] = 0.f;

        #pragma unroll
        for (int ch = 0; ch < KCH; ch++) {
            uint32_t a0, a1, a2, a3;
            LDSM4(a0, a1, a2, a3, Ard + ch * 32);
            #pragma unroll
            for (int tp = 0; tp < 4; tp++) {
                uint32_t r0, r1, r2, r3;
                LDSM4(r0, r1, r2, r3, b_lane + (uint32_t)(tp * (16 * WSTR * 2) + ch * 32));
                MMA16816(C[2 * tp],     a0, a1, a2, a3, r0, r1);
                MMA16816(C[2 * tp + 1], a0, a1, a2, a3, r2, r3);
            }
        }

        __half* Aw = reinterpret_cast<__half*>(smem + SMEM_A0 + (rb ^ 1) * A_BYTES);

        // ---- gate regroup (1 xor-1 exchange) + activations + h writeback ----
        #pragma unroll
        for (int ti = 0; ti < 8; ti++) {
            // even m lanes hold (i,f); odd hold (g,o). Exchange the half each
            // side doesn't need so every lane gets all 4 gates of one (row,j).
            float s0 = (l & 1) ? C[ti][0] : C[ti][2];
            float s1 = (l & 1) ? C[ti][1] : C[ti][3];
            float r0 = __shfl_xor_sync(0xffffffffu, s0, 1);
            float r1 = __shfl_xor_sync(0xffffffffu, s1, 1);
            float gi, gf, gg, go;
            if (l & 1) { gi = r0;       gf = r1;       gg = C[ti][2]; go = C[ti][3]; }
            else       { gi = C[ti][0]; gf = C[ti][1]; gg = r0;       go = r1;       }
            float cc = fmaf(siga(gf), c_st[ti], siga(gi) * tanha(gg));
            c_st[ti] = cc;
            float hh = siga(go) * tanha(cc);
            if (t == TSTEPS - 1) p_out = fmaf(hh, wl[ti], p_out);
            int jglob = 16 * w + 2 * ti + (m >> 1);
            Aw[rowm * WSTR + jglob] = __float2half_rn(hh);
        }
        if (dox) Aw[xr * WSTR + HID + xi] = __float2half_rn(xv);
    }

    // ---- epilogue: out[b] = h_n . W_lin + b_lin ----
    p_out += __shfl_xor_sync(0xffffffffu, p_out, 2);   // lanes m0+m2 / m1+m3 (same row)
    float* P = reinterpret_cast<float*>(smem + SMEM_P);
    if (m < 2) P[rowm * 8 + w] = p_out;
    __syncthreads();
    if (tid < MB) {
        float s = b_lin[0];
        #pragma unroll
        for (int ww = 0; ww < 8; ww++) s += P[tid * 8 + ww];
        out[b0 + tid] = s;
    }
}

extern "C" void kernel_launch(void* const* d_in, const int* in_sizes, int n_in,
                              void* d_out, int out_size) {
    const float* x     = (const float*)d_in[0];
    const float* W_ih  = (const float*)d_in[1];
    const float* W_hh  = (const float*)d_in[2];
    const float* b_ih  = (const float*)d_in[3];
    const float* b_hh  = (const float*)d_in[4];
    const float* W_lin = (const float*)d_in[5];
    const float* b_lin = (const float*)d_in[6];
    float* out = (float*)d_out;

    int B    = in_sizes[0] / TI;   // 2048
    int nCTA = B / MB;             // 128 CTAs, one wave

    cudaFuncSetAttribute(lstm_hmma,
                         cudaFuncAttributeMaxDynamicSharedMemorySize, SMEM_TOTAL);
    lstm_hmma<<<nCTA, TPB, SMEM_TOTAL>>>(x, W_ih, W_hh, b_ih, b_hh,
                                         W_lin, b_lin, out);
}

// round 10
// speedup vs baseline: 9.4428x; 1.2903x over previous
#include <cuda_runtime.h>
#include <cuda_fp16.h>
#include <cstdint>
#include <cstddef>

#define TPB     512
#define NW      16            // warps, each owns N=32 gate cols
#define MB      16            // batch rows per CTA
#define TSTEPS  512
#define ISZ     5
#define TI      (TSTEPS*ISZ)
#define HID     128
#define KTOT    144           // 128 h + 5 x + 1 bias + 10 zero pad
#define KCH     9             // K chunks of 16
#define WSTR    152           // halves per row (304B stride: ldmatrix conflict-free)

#define B_BYTES   (512*WSTR*2)        // 155648 (staging only; B lives in regs)
#define A_BYTES   (MB*WSTR*2)         // 4864 per buffer
#define SMEM_B    0
#define SMEM_A0   B_BYTES
#define SMEM_A1   (SMEM_A0 + A_BYTES)
#define SMEM_P    (SMEM_A1 + A_BYTES)
#define SMEM_TOTAL (SMEM_P + MB*NW*4) // 166400

__device__ __forceinline__ uint32_t smem_u32(const void* p) {
    uint32_t a;
    asm("{ .reg .u64 t; cvta.to.shared.u64 t, %1; cvt.u32.u64 %0, t; }" : "=r"(a) : "l"(p));
    return a;
}
#define LDSM4(r0, r1, r2, r3, addr) \
    asm volatile("ldmatrix.sync.aligned.m8n8.x4.shared.b16 {%0,%1,%2,%3}, [%4];" \
        : "=r"(r0), "=r"(r1), "=r"(r2), "=r"(r3) : "r"(addr))
#define MMA16816(d, a0, a1, a2, a3, b0, b1) \
    asm volatile("mma.sync.aligned.m16n8k16.row.col.f32.f16.f16.f32 " \
        "{%0,%1,%2,%3}, {%4,%5,%6,%7}, {%8,%9}, {%0,%1,%2,%3};" \
        : "+f"((d)[0]), "+f"((d)[1]), "+f"((d)[2]), "+f"((d)[3]) \
        : "r"(a0), "r"(a1), "r"(a2), "r"(a3), "r"(b0), "r"(b1))

__device__ __forceinline__ float tanha(float x) {
    float r; asm("tanh.approx.f32 %0, %1;" : "=f"(r) : "f"(x)); return r;
}
__device__ __forceinline__ float siga(float x) {
    return fmaf(0.5f, tanha(0.5f * x), 0.5f);
}

__global__ void __launch_bounds__(TPB, 1)
lstm_hmma(const float* __restrict__ x,     const float* __restrict__ W_ih,
          const float* __restrict__ W_hh,  const float* __restrict__ b_ih,
          const float* __restrict__ b_hh,  const float* __restrict__ W_lin,
          const float* __restrict__ b_lin, float* __restrict__ out)
{
    extern __shared__ char smem[];
    const uint32_t sb = smem_u32(smem);
    const int tid = threadIdx.x;
    const int w = tid >> 5, l = tid & 31;
    const int q = l >> 2, m = l & 3;
    const int b0 = blockIdx.x * MB;

    // ---- stage B = W into SMEM (transient), fp16 [n][k], n = j*4 + g ----
    for (int e = tid; e < 512 * KTOT; e += TPB) {
        int ni = e / KTOT, k = e - ni * KTOT;
        int g = ni & 3, j = ni >> 2;
        int nsrc = g * HID + j;
        float v = 0.f;
        if (k < HID)        v = W_hh[nsrc * HID + k];
        else if (k < 133)   v = W_ih[nsrc * ISZ + (k - HID)];
        else if (k == 133)  v = b_ih[nsrc] + b_hh[nsrc];
        *reinterpret_cast<__half*>(smem + SMEM_B + (size_t)(ni * WSTR + k) * 2) = __float2half(v);
    }
    __syncthreads();

    // ---- hoist this warp's B slice (N=32) into registers: 9 chunks x 8 regs ----
    uint32_t Bq[KCH][8];
    {
        const uint32_t bl = sb + SMEM_B +
            (uint32_t)(((32 * w + ((l >> 4) & 1) * 8 + (l & 7)) * WSTR + ((l >> 3) & 1) * 8) * 2);
        #pragma unroll
        for (int ch = 0; ch < KCH; ch++) {
            LDSM4(Bq[ch][0], Bq[ch][1], Bq[ch][2], Bq[ch][3], bl + ch * 32);
            LDSM4(Bq[ch][4], Bq[ch][5], Bq[ch][6], Bq[ch][7],
                  bl + (uint32_t)(16 * WSTR * 2) + ch * 32);
        }
    }
    __syncthreads();

    // ---- init A buffers: zero, bias col (both), x(t=0) into buffer 0 ----
    for (int i = tid; i < 2 * A_BYTES / 4; i += TPB)
        reinterpret_cast<uint32_t*>(smem + SMEM_A0)[i] = 0u;
    __syncthreads();
    if (tid < MB) {
        *reinterpret_cast<__half*>(smem + SMEM_A0 + (tid * WSTR + 133) * 2) = __float2half(1.f);
        *reinterpret_cast<__half*>(smem + SMEM_A1 + (tid * WSTR + 133) * 2) = __float2half(1.f);
    }
    if (tid < MB * ISZ) {
        int r = tid / ISZ, i = tid - r * ISZ;
        *reinterpret_cast<__half*>(smem + SMEM_A0 + (r * WSTR + HID + i) * 2) =
            __float2half(x[(size_t)(b0 + r) * TI + i]);
    }

    // A x4 lane address: [rows0-7 klo, rows8-15 klo, rows0-7 khi, rows8-15 khi]
    const uint32_t a_lane = sb + SMEM_A0 +
        (uint32_t)(((((l >> 3) & 1) * 8 + (l & 7)) * WSTR + ((l >> 4) & 1) * 8) * 2);

    const int rowm = q + 8 * (m & 1);   // lane's output row after gate exchange
    float wl[4], c_st[4];
    #pragma unroll
    for (int tp = 0; tp < 4; tp++) {
        wl[tp] = W_lin[8 * w + 2 * tp + (m >> 1)];
        c_st[tp] = 0.f;
    }
    float p_out = 0.f;

    for (int t = 0; t < TSTEPS; t++) {
        __syncthreads();                     // A[read buffer] fully written
        const int rb = t & 1;
        const uint32_t Ard = a_lane + (uint32_t)(rb ? A_BYTES : 0);

        // x(t+1) prefetch (LDG early; stored into write buffer later)
        float xv = 0.f; int xr = 0, xi = 0;
        const bool dox = (tid < MB * ISZ) && (t + 1 < TSTEPS);
        if (dox) {
            xr = tid / ISZ; xi = tid - xr * ISZ;
            xv = x[(size_t)(b0 + xr) * TI + (size_t)(t + 1) * ISZ + xi];
        }

        float C[4][4];
        #pragma unroll
        for (int tp = 0; tp < 4; tp++)
            C[tp][0] = C[tp][1] = C[tp][2] = C[tp][3] = 0.f;

        #pragma unroll
        for (int ch = 0; ch < KCH; ch++) {
            uint32_t a0, a1, a2, a3;
            LDSM4(a0, a1, a2, a3, Ard + ch * 32);
            MMA16816(C[0], a0, a1, a2, a3, Bq[ch][0], Bq[ch][1]);
            MMA16816(C[1], a0, a1, a2, a3, Bq[ch][2], Bq[ch][3]);
            MMA16816(C[2], a0, a1, a2, a3, Bq[ch][4], Bq[ch][5]);
            MMA16816(C[3], a0, a1, a2, a3, Bq[ch][6], Bq[ch][7]);
        }

        __half* Aw = reinterpret_cast<__half*>(smem + SMEM_A0 + (rb ^ 1) * A_BYTES);

        // ---- gate regroup (1 xor-1 exchange) + activations + h writeback ----
        #pragma unroll
        for (int tp = 0; tp < 4; tp++) {
            // even-m lanes hold (i,f) both rows; odd-m hold (g,o). Exchange the
            // row-half each side doesn't need -> every lane owns one full (row,j).
            float s0 = (l & 1) ? C[tp][0] : C[tp][2];
            float s1 = (l & 1) ? C[tp][1] : C[tp][3];
            float r0 = __shfl_xor_sync(0xffffffffu, s0, 1);
            float r1 = __shfl_xor_sync(0xffffffffu, s1, 1);
            float gi, gf, gg, go;
            if (l & 1) { gi = r0;        gf = r1;        gg = C[tp][2]; go = C[tp][3]; }
            else       { gi = C[tp][0];  gf = C[tp][1];  gg = r0;       go = r1;       }
            float cc = fmaf(siga(gf), c_st[tp], siga(gi) * tanha(gg));
            c_st[tp] = cc;
            float hh = siga(go) * tanha(cc);
            if (t == TSTEPS - 1) p_out = fmaf(hh, wl[tp], p_out);
            int jglob = 8 * w + 2 * tp + (m >> 1);
            Aw[rowm * WSTR + jglob] = __float2half_rn(hh);
        }
        if (dox) Aw[xr * WSTR + HID + xi] = __float2half_rn(xv);
    }

    // ---- epilogue: out[b] = h_n . W_lin + b_lin ----
    p_out += __shfl_xor_sync(0xffffffffu, p_out, 2);   // m0+m2 (row q), m1+m3 (row q+8)
    float* P = reinterpret_cast<float*>(smem + SMEM_P);
    if (m < 2) P[rowm * NW + w] = p_out;
    __syncthreads();
    if (tid < MB) {
        float s = b_lin[0];
        #pragma unroll
        for (int ww = 0; ww < NW; ww++) s += P[tid * NW + ww];
        out[b0 + tid] = s;
    }
}

extern "C" void kernel_launch(void* const* d_in, const int* in_sizes, int n_in,
                              void* d_out, int out_size) {
    const float* x     = (const float*)d_in[0];
    const float* W_ih  = (const float*)d_in[1];
    const float* W_hh  = (const float*)d_in[2];
    const float* b_ih  = (const float*)d_in[3];
    const float* b_hh  = (const float*)d_in[4];
    const float* W_lin = (const float*)d_in[5];
    const float* b_lin = (const float*)d_in[6];
    float* out = (float*)d_out;

    int B    = in_sizes[0] / TI;   // 2048
    int nCTA = B / MB;             // 128 CTAs, one wave

    cudaFuncSetAttribute(lstm_hmma,
                         cudaFuncAttributeMaxDynamicSharedMemorySize, SMEM_TOTAL);
    lstm_hmma<<<nCTA, TPB, SMEM_TOTAL>>>(x, W_ih, W_hh, b_ih, b_hh,
                                         W_lin, b_lin, out);
}

// round 11
// speedup vs baseline: 10.5996x; 1.1225x over previous
#include <cuda_runtime.h>
#include <cuda_fp16.h>
#include <cstdint>
#include <cstddef>

#define TPB     512
#define NW      16            // warps; each owns 8 hidden cols x 4 gates (N=32)
#define MB      16            // batch rows per CTA
#define TSTEPS  512
#define ISZ     5
#define TI      (TSTEPS*ISZ)
#define HID     128
#define KTOT    144           // 128 h + 5 x + 1 bias + 10 zero pad
#define KCH     9             // K chunks of 16
#define WSTR    152           // halves per row (304B stride: ldmatrix conflict-free)

#define B_BYTES   (512*WSTR*2)        // staging for B (stays resident, read once)
#define A_BYTES   (MB*WSTR*2)         // 4864 per buffer
#define SMEM_B    0
#define SMEM_A0   B_BYTES
#define SMEM_A1   (SMEM_A0 + A_BYTES)
#define SMEM_TOTAL (SMEM_A1 + A_BYTES)

__device__ __forceinline__ uint32_t smem_u32(const void* p) {
    uint32_t a;
    asm("{ .reg .u64 t; cvta.to.shared.u64 t, %1; cvt.u32.u64 %0, t; }" : "=r"(a) : "l"(p));
    return a;
}
#define LDSM4(r0, r1, r2, r3, addr) \
    asm volatile("ldmatrix.sync.aligned.m8n8.x4.shared.b16 {%0,%1,%2,%3}, [%4];" \
        : "=r"(r0), "=r"(r1), "=r"(r2), "=r"(r3) : "r"(addr))
#define MMA16816(d, a0, a1, a2, a3, b0, b1) \
    asm volatile("mma.sync.aligned.m16n8k16.row.col.f32.f16.f16.f32 " \
        "{%0,%1,%2,%3}, {%4,%5,%6,%7}, {%8,%9}, {%0,%1,%2,%3};" \
        : "+f"((d)[0]), "+f"((d)[1]), "+f"((d)[2]), "+f"((d)[3]) \
        : "r"(a0), "r"(a1), "r"(a2), "r"(a3), "r"(b0), "r"(b1))

__device__ __forceinline__ float tanha(float x) {
    float r; asm("tanh.approx.f32 %0, %1;" : "=f"(r) : "f"(x)); return r;
}
__device__ __forceinline__ float siga(float x) {
    return fmaf(0.5f, tanha(0.5f * x), 0.5f);
}

__global__ void __launch_bounds__(TPB, 1)
lstm_hmma(const float* __restrict__ x,     const float* __restrict__ W_ih,
          const float* __restrict__ W_hh,  const float* __restrict__ b_ih,
          const float* __restrict__ b_hh,  const float* __restrict__ W_lin,
          const float* __restrict__ b_lin, float* __restrict__ out)
{
    extern __shared__ char smem[];
    const uint32_t sb = smem_u32(smem);
    const int tid = threadIdx.x;
    const int w = tid >> 5, l = tid & 31;
    const int q = l >> 2, m = l & 3;     // C rows q,q+8; cols 2m,2m+1 (within tile)
    const int b0 = blockIdx.x * MB;
    const int j0 = 8 * w + 2 * m;        // this lane's hidden col pair

    // ---- stage B = W, fp16 [ni][k], ni = w*32 + g*8 + jj  (gate = tile) ----
    for (int e = tid; e < 512 * KTOT; e += TPB) {
        int ni = e / KTOT, k = e - ni * KTOT;
        int wb = ni >> 5, rem = ni & 31;
        int g = rem >> 3, jj = rem & 7;
        int nsrc = g * HID + wb * 8 + jj;
        float v = 0.f;
        if (k < HID)        v = W_hh[nsrc * HID + k];
        else if (k < 133)   v = W_ih[nsrc * ISZ + (k - HID)];
        else if (k == 133)  v = b_ih[nsrc] + b_hh[nsrc];
        *reinterpret_cast<__half*>(smem + SMEM_B + (size_t)(ni * WSTR + k) * 2) = __float2half(v);
    }
    __syncthreads();

    // ---- hoist this warp's B slice into registers: 9 chunks x 8 regs ----
    // Bq[ch][0,1]=gate i, [2,3]=gate f, [4,5]=gate g, [6,7]=gate o
    uint32_t Bq[KCH][8];
    {
        const uint32_t bl = sb + SMEM_B +
            (uint32_t)(((32 * w + ((l >> 4) & 1) * 8 + (l & 7)) * WSTR + ((l >> 3) & 1) * 8) * 2);
        #pragma unroll
        for (int ch = 0; ch < KCH; ch++) {
            LDSM4(Bq[ch][0], Bq[ch][1], Bq[ch][2], Bq[ch][3], bl + ch * 32);
            LDSM4(Bq[ch][4], Bq[ch][5], Bq[ch][6], Bq[ch][7],
                  bl + (uint32_t)(16 * WSTR * 2) + ch * 32);
        }
    }
    __syncthreads();

    // ---- init A buffers: zero, bias col (both), x(t=0) into buffer 0 ----
    for (int i = tid; i < 2 * A_BYTES / 4; i += TPB)
        reinterpret_cast<uint32_t*>(smem + SMEM_A0)[i] = 0u;
    __syncthreads();
    if (tid < MB) {
        *reinterpret_cast<__half*>(smem + SMEM_A0 + (tid * WSTR + 133) * 2) = __float2half(1.f);
        *reinterpret_cast<__half*>(smem + SMEM_A1 + (tid * WSTR + 133) * 2) = __float2half(1.f);
    }
    if (tid < MB * ISZ) {
        int r = tid / ISZ, i = tid - r * ISZ;
        *reinterpret_cast<__half*>(smem + SMEM_A0 + (r * WSTR + HID + i) * 2) =
            __float2half(x[(size_t)(b0 + r) * TI + i]);
    }

    // A x4 lane address: [rows0-7 klo, rows8-15 klo, rows0-7 khi, rows8-15 khi]
    const uint32_t a_lane0 = sb + SMEM_A0 +
        (uint32_t)(((((l >> 3) & 1) * 8 + (l & 7)) * WSTR + ((l >> 4) & 1) * 8) * 2);
    const uint32_t a_lane1 = a_lane0 + A_BYTES;

    float c_st[4];
    c_st[0] = c_st[1] = c_st[2] = c_st[3] = 0.f;

    for (int t = 0; t < TSTEPS; t++) {
        __syncthreads();                       // A[read buffer] fully written
        const uint32_t Ard = (t & 1) ? a_lane1 : a_lane0;

        // x(t+1) prefetch (LDG early; stored into write buffer later)
        float xv = 0.f; int xr = 0, xi = 0;
        const bool dox = (tid < MB * ISZ) && (t + 1 < TSTEPS);
        if (dox) {
            xr = tid / ISZ; xi = tid - xr * ISZ;
            xv = x[(size_t)(b0 + xr) * TI + (size_t)(t + 1) * ISZ + xi];
        }

        float Ci[4], Cf[4], Cg[4], Co[4];
        #pragma unroll
        for (int u = 0; u < 4; u++) { Ci[u] = 0.f; Cf[u] = 0.f; Cg[u] = 0.f; Co[u] = 0.f; }

        #pragma unroll
        for (int ch = 0; ch < KCH; ch++) {
            uint32_t a0, a1, a2, a3;
            LDSM4(a0, a1, a2, a3, Ard + ch * 32);
            MMA16816(Ci, a0, a1, a2, a3, Bq[ch][0], Bq[ch][1]);
            MMA16816(Cf, a0, a1, a2, a3, Bq[ch][2], Bq[ch][3]);
            MMA16816(Cg, a0, a1, a2, a3, Bq[ch][4], Bq[ch][5]);
            MMA16816(Co, a0, a1, a2, a3, Bq[ch][6], Bq[ch][7]);
        }

        __half* Aw = reinterpret_cast<__half*>(
            smem + SMEM_A0 + ((t & 1) ^ 1) * A_BYTES);

        // ---- activations: no shfl (lane owns all 4 gates of its 4 h-units) ----
        // c-part first (12 independent MUFU), then o-part
        float cc[4];
        #pragma unroll
        for (int u = 0; u < 4; u++) {
            cc[u] = fmaf(siga(Cf[u]), c_st[u], siga(Ci[u]) * tanha(Cg[u]));
            c_st[u] = cc[u];
        }
        float hh[4];
        #pragma unroll
        for (int u = 0; u < 4; u++)
            hh[u] = siga(Co[u]) * tanha(cc[u]);

        // h writeback: units 0,1 -> (row q, j0/j0+1); units 2,3 -> (row q+8)
        *reinterpret_cast<__half2*>(&Aw[q * WSTR + j0]) =
            __floats2half2_rn(hh[0], hh[1]);
        *reinterpret_cast<__half2*>(&Aw[(q + 8) * WSTR + j0]) =
            __floats2half2_rn(hh[2], hh[3]);

        if (dox) Aw[xr * WSTR + HID + xi] = __float2half_rn(xv);
    }

    __syncthreads();
    // ---- epilogue: final h is in buffer 0 (t=511 wrote rb^1 = 0) ----
    if (tid < 128) {
        const int row = tid >> 3, seg = tid & 7;
        const __half* Hf = reinterpret_cast<const __half*>(smem + SMEM_A0);
        float s = 0.f;
        #pragma unroll
        for (int jj = 0; jj < 16; jj++) {
            int j = seg * 16 + jj;
            s += __half2float(Hf[row * WSTR + j]) * W_lin[j];
        }
        s += __shfl_xor_sync(0xffffffffu, s, 4);
        s += __shfl_xor_sync(0xffffffffu, s, 2);
        s += __shfl_xor_sync(0xffffffffu, s, 1);
        if (seg == 0) out[b0 + row] = s + b_lin[0];
    }
}

extern "C" void kernel_launch(void* const* d_in, const int* in_sizes, int n_in,
                              void* d_out, int out_size) {
    const float* x     = (const float*)d_in[0];
    const float* W_ih  = (const float*)d_in[1];
    const float* W_hh  = (const float*)d_in[2];
    const float* b_ih  = (const float*)d_in[3];
    const float* b_hh  = (const float*)d_in[4];
    const float* W_lin = (const float*)d_in[5];
    const float* b_lin = (const float*)d_in[6];
    float* out = (float*)d_out;

    int B    = in_sizes[0] / TI;   // 2048
    int nCTA = B / MB;             // 128 CTAs, one wave

    cudaFuncSetAttribute(lstm_hmma,
                         cudaFuncAttributeMaxDynamicSharedMemorySize, SMEM_TOTAL);
    lstm_hmma<<<nCTA, TPB, SMEM_TOTAL>>>(x, W_ih, W_hh, b_ih, b_hh,
                                         W_lin, b_lin, out);
}